// round 13
// baseline (speedup 1.0000x reference)
#include <cuda_runtime.h>
#include <cuda_bf16.h>
#include <cstdint>
#include <math.h>

// Problem constants
#define BATCH 32
#define C_IN  64
#define T_LEN 256
#define ZDIM  32
#define HID0  256
#define HID1  256
#define COUT2 96          // 3*Z
#define MU_ELEMS (BATCH*ZDIM*T_LEN)            // 262144

typedef unsigned long long u64;

// Scratch (no allocations allowed -> __device__ globals)
// Activations stored DUPLICATED: element t = float2{v,v} (u64) so packed-f32x2
// operands load directly from smem with no splat MOVs.
__device__ u64  g_xd[BATCH * C_IN * T_LEN];        // 4 MB  (dup of input x)
__device__ u64  g_h0[BATCH * HID0 * T_LEN];        // 16 MB (dup)
__device__ u64  g_h1[BATCH * HID1 * T_LEN];        // 16 MB (dup)
__device__ float g_stats[BATCH * COUT2 * T_LEN];   // 3 MB  (normal)
__device__ float g_wt0[192 * 256];                 // W0 transposed [i*3+k][o]
__device__ float g_wt1[768 * 256];                 // W1 transposed
__device__ float g_wt2[768 * 96];                  // W2 transposed (exact)

// ---------------------------------------------------------------------------
// packed-f32x2 helpers (FFMA2: only reachable via PTX fma.rn.f32x2)
// ---------------------------------------------------------------------------
__device__ __forceinline__ void fma2(u64& d, u64 a, u64 b) {
    asm("fma.rn.f32x2 %0,%1,%2,%0;" : "+l"(d) : "l"(a), "l"(b));
}
__device__ __forceinline__ float2 unpk(u64 v) {
    float2 f; asm("mov.b64 {%0,%1},%2;" : "=f"(f.x), "=f"(f.y) : "l"(v)); return f;
}
__device__ __forceinline__ u64 dup2(float x) {
    u64 r; asm("mov.b64 %0,{%1,%1};" : "=l"(r) : "f"(x)); return r;
}

// ---------------------------------------------------------------------------
// cp.async helpers
// ---------------------------------------------------------------------------
__device__ __forceinline__ unsigned int s2u(const void* p) {
    unsigned int a;
    asm("{.reg .u64 t; cvta.to.shared.u64 t,%1; cvt.u32.u64 %0,t;}" : "=r"(a) : "l"(p));
    return a;
}
__device__ __forceinline__ void cp16(void* d, const void* s) {
    asm volatile("cp.async.ca.shared.global [%0],[%1],16;" :: "r"(s2u(d)), "l"(s));
}
__device__ __forceinline__ void cp8z(void* d, const void* s, bool v) {
    int sz = v ? 8 : 0;      // src-size 0 -> zero-fill, no read
    asm volatile("cp.async.ca.shared.global [%0],[%1],8,%2;" :: "r"(s2u(d)), "l"(s), "r"(sz));
}
#define CP_COMMIT() asm volatile("cp.async.commit_group;")

// ---------------------------------------------------------------------------
// Pre-kernel: transpose weights W[o][i][k] -> Wt[(i*3+k)][o]  AND  dup input x.
// ---------------------------------------------------------------------------
__global__ __launch_bounds__(256)
void prep_kernel(const float* __restrict__ x,
                 const float* __restrict__ W0, const float* __restrict__ W1,
                 const float* __restrict__ W2)
{
    int e = blockIdx.x * 256 + threadIdx.x;
    const int N0 = 192 * 256, N1 = 768 * 256, N2 = 768 * 96;
    const int NX = BATCH * C_IN * T_LEN;
    if (e < N0) {
        int r = e >> 8, o = e & 255;
        int i = r / 3, k = r - 3 * i;
        g_wt0[e] = W0[(o * 64 + i) * 3 + k];
    } else if (e < N0 + N1) {
        int e1 = e - N0;
        int r = e1 >> 8, o = e1 & 255;
        int i = r / 3, k = r - 3 * i;
        g_wt1[e1] = W1[(o * 256 + i) * 3 + k];
    } else if (e < N0 + N1 + N2) {
        int e2 = e - N0 - N1;
        int r = e2 / 96, o = e2 - 96 * r;
        int i = r / 3, k = r - 3 * i;
        g_wt2[e2] = W2[(o * 256 + i) * 3 + k];
    } else if (e < N0 + N1 + N2 + NX) {
        int e3 = e - N0 - N1 - N2;
        g_xd[e3] = dup2(x[e3]);
    }
}

// ---------------------------------------------------------------------------
// Conv1d (K=3, SAME) tiled GEMM, packed-f32x2, 3-stage cp.async pipeline,
// DUPLICATED activation layout (no splat MOVs in the inner loop).
// 128 threads.  Tile 32 o x 64 t, micro-tile 4o x 4t, CI=8.
// Xs (u64) cols: [0,64)=t=bt+c, col 64=t=bt+64, col 65=t=bt-1.
// ---------------------------------------------------------------------------
template<int CIN, bool DUPOUT>
__global__ __launch_bounds__(128, 8)
void conv_kernel(const u64* __restrict__ X, const float* __restrict__ Wt,
                 const float* __restrict__ Bias, void* __restrict__ Yv,
                 int COUT, int WSTRIDE)
{
    constexpr int TILE_O = 32;
    constexpr int TILE_T = 64;
    constexpr int CI   = 8;
    constexpr int NIT  = CIN / CI;     // >= 3
    constexpr int XCOL = 68;           // 66 used, pad for 16B row alignment
    constexpr int TTHR = TILE_T / 4;   // 16 threads along t

    __shared__ __align__(16) u64   Xs[3][CI][XCOL];
    __shared__ __align__(16) float Ws[3][CI * 3][TILE_O];

    const int tid = threadIdx.x;
    const int tx  = tid % TTHR;
    const int ty  = tid / TTHR;        // 0..7
    const int bt  = blockIdx.x * TILE_T;
    const int bo  = blockIdx.y * TILE_O;
    const int b   = blockIdx.z;

    const u64* Xb = X + (size_t)b * CIN * T_LEN;

    auto load_stage = [&](int ci0, int s) {
        const u64* xb = Xb + (size_t)ci0 * T_LEN;
        // main X tile: CI rows x 64 cols of u64 = 256 16B-chunks (exactly 2/thread)
#pragma unroll
        for (int q = 0; q < 2; ++q) {
            int idx = tid + q * 128;
            int row = idx >> 5, c2 = idx & 31;       // chunk = 2 u64
            cp16(&Xs[s][row][2 * c2], xb + row * T_LEN + bt + 2 * c2);
        }
        // halos: side 0 -> col 64 (t=bt+64), side 1 -> col 65 (t=bt-1)
        if (tid < CI * 2) {
            int row = tid >> 1, side = tid & 1;
            int t = side ? (bt - 1) : (bt + TILE_T);
            bool ok = (t >= 0) && (t < T_LEN);
            cp8z(&Xs[s][row][TILE_T + side], xb + row * T_LEN + (ok ? t : 0), ok);
        }
        // W tile: 24 rows x 32 cols = 192 16B-chunks (guarded: NOT a full 2/thread)
        for (int idx = tid; idx < CI * 3 * TILE_O / 4; idx += 128) {
            int row = idx >> 3, c4 = idx & 7;
            cp16(&Ws[s][row][4 * c4],
                 Wt + (size_t)(3 * ci0 + row) * WSTRIDE + bo + 4 * c4);
        }
    };

    u64 acc[2][4];
#pragma unroll
    for (int p = 0; p < 2; ++p)
#pragma unroll
        for (int t = 0; t < 4; ++t) acc[p][t] = 0ull;

    load_stage(0,  0); CP_COMMIT();
    load_stage(CI, 1); CP_COMMIT();

#pragma unroll 1
    for (int it = 0; it < NIT; ++it) {
        if (it < NIT - 1) asm volatile("cp.async.wait_group 1;");
        else              asm volatile("cp.async.wait_group 0;");
        __syncthreads();                       // stage 'it' visible; compute(it-1) retired
        if (it + 2 < NIT) { load_stage((it + 2) * CI, (it + 2) % 3); CP_COMMIT(); }

        const int s = it % 3;
#pragma unroll
        for (int il = 0; il < CI; ++il) {
            // dup operands straight from smem: no splats
            u64 xs[6];
            xs[0] = Xs[s][il][tx ? 4 * tx - 1 : 65];            // x[t0-1]
            ulonglong2 A = *(const ulonglong2*)&Xs[s][il][4 * tx];      // x[t0],x[t0+1]
            ulonglong2 B = *(const ulonglong2*)&Xs[s][il][4 * tx + 2];  // x[t0+2],x[t0+3]
            xs[1] = A.x; xs[2] = A.y; xs[3] = B.x; xs[4] = B.y;
            xs[5] = Xs[s][il][4 * tx + 4];                      // x[t0+4] (halo col for tx=15)
#pragma unroll
            for (int k = 0; k < 3; ++k) {
                ulonglong2 w = *(const ulonglong2*)&Ws[s][il * 3 + k][4 * ty];
#pragma unroll
                for (int tt = 0; tt < 4; ++tt) {
                    fma2(acc[0][tt], w.x, xs[tt + k]);
                    fma2(acc[1][tt], w.y, xs[tt + k]);
                }
            }
        }
    }

    // epilogue: unpack pairs, bias (+relu for DUPOUT layers)
#pragma unroll
    for (int p = 0; p < 2; ++p) {
        int o0 = bo + 4 * ty + 2 * p;
        float blo = Bias[o0];
        float bhi = Bias[o0 + 1];
        float lo[4], hi[4];
#pragma unroll
        for (int tt = 0; tt < 4; ++tt) {
            float2 f = unpk(acc[p][tt]);
            lo[tt] = f.x + blo;
            hi[tt] = f.y + bhi;
            if (DUPOUT) { lo[tt] = fmaxf(lo[tt], 0.f); hi[tt] = fmaxf(hi[tt], 0.f); }
        }
        if (DUPOUT) {
            // duplicated store: float4{v,v,w,w} x2 per o-row
            float2* yp = (float2*)Yv + ((size_t)b * COUT + o0) * T_LEN + bt + 4 * tx;
            *(float4*)&yp[0]          = make_float4(lo[0], lo[0], lo[1], lo[1]);
            *(float4*)&yp[2]          = make_float4(lo[2], lo[2], lo[3], lo[3]);
            *(float4*)&yp[T_LEN]      = make_float4(hi[0], hi[0], hi[1], hi[1]);
            *(float4*)&yp[T_LEN + 2]  = make_float4(hi[2], hi[2], hi[3], hi[3]);
        } else {
            float* yp = (float*)Yv + ((size_t)b * COUT + o0) * T_LEN + bt + 4 * tx;
            *(float4*)yp           = make_float4(lo[0], lo[1], lo[2], lo[3]);
            *(float4*)(yp + T_LEN) = make_float4(hi[0], hi[1], hi[2], hi[3]);
        }
    }
}

__device__ __forceinline__ float softplus_f(float x)
{
    return fmaxf(x, 0.f) + log1pf(expf(-fabsf(x)));
}

// ---------------------------------------------------------------------------
// Triangular fill + fused mu copy.
// cov_u[c][r] = (1/d_r) * prod_{k=c}^{r-1} (-s_k/d_k); scale_tril[r][c]=cov_u[c][r].
// Thread = 4 consecutive columns (float4 STG.cs). Block = 4 (b,z) pairs x 64 thr.
// ---------------------------------------------------------------------------
__global__ __launch_bounds__(256)
void tri_kernel(const float* __restrict__ stats, float* __restrict__ out)
{
    __shared__ float invd[4][256];
    __shared__ float gs[4][256];

    const int tid  = threadIdx.x;
    const int sub  = tid >> 6;
    const int lane = tid & 63;
    const int bz   = blockIdx.x * 4 + sub;
    const int b    = bz >> 5;
    const int z    = bz & 31;
    const int c0   = lane * 4;

    // fused mu copy
    {
        float4 mv = *(const float4*)(stats + ((size_t)b * COUT2 + z) * T_LEN + c0);
        __stcs((float4*)(out + ((size_t)bz << 8) + c0), mv);
    }

    const float* sd = stats + ((size_t)b * COUT2 + 32 + 2 * z) * T_LEN;
    const float* ss = sd + T_LEN;

    float4 dv = *(const float4*)(sd + c0);
    float4 sv = *(const float4*)(ss + c0);
    float d0 = softplus_f(dv.x) + 1.f, d1 = softplus_f(dv.y) + 1.f;
    float d2 = softplus_f(dv.z) + 1.f, d3 = softplus_f(dv.w) + 1.f;
    float s0 = (c0 + 0 < 255) ? softplus_f(sv.x) : 0.f;
    float s1 = (c0 + 1 < 255) ? softplus_f(sv.y) : 0.f;
    float s2 = (c0 + 2 < 255) ? softplus_f(sv.z) : 0.f;
    float s3 = (c0 + 3 < 255) ? softplus_f(sv.w) : 0.f;
    invd[sub][c0 + 0] = 1.f / d0;  gs[sub][c0 + 0] = -s0 / d0;
    invd[sub][c0 + 1] = 1.f / d1;  gs[sub][c0 + 1] = -s1 / d1;
    invd[sub][c0 + 2] = 1.f / d2;  gs[sub][c0 + 2] = -s2 / d2;
    invd[sub][c0 + 3] = 1.f / d3;  gs[sub][c0 + 3] = -s3 / d3;
    __syncthreads();

    float p0 = 1.f, p1 = 1.f, p2 = 1.f, p3 = 1.f;
    float* op = out + MU_ELEMS + ((size_t)bz << 16) + c0;

#pragma unroll 4
    for (int r = 0; r < 256; ++r) {
        float iv = invd[sub][r];
        float gv = gs[sub][r];
        float4 v = make_float4(0.f, 0.f, 0.f, 0.f);
        if (r >= c0)     { v.x = p0 * iv; if (!isfinite(v.x)) v.x = 0.f; p0 *= gv; }
        if (r >= c0 + 1) { v.y = p1 * iv; if (!isfinite(v.y)) v.y = 0.f; p1 *= gv; }
        if (r >= c0 + 2) { v.z = p2 * iv; if (!isfinite(v.z)) v.z = 0.f; p2 *= gv; }
        if (r >= c0 + 3) { v.w = p3 * iv; if (!isfinite(v.w)) v.w = 0.f; p3 *= gv; }
        __stcs((float4*)&op[(size_t)r << 8], v);
    }
}

// ---------------------------------------------------------------------------
extern "C" void kernel_launch(void* const* d_in, const int* in_sizes, int n_in,
                              void* d_out, int out_size)
{
    const float* x  = (const float*)d_in[0];
    const float* W0 = (const float*)d_in[1];
    const float* b0 = (const float*)d_in[2];
    const float* W1 = (const float*)d_in[3];
    const float* b1 = (const float*)d_in[4];
    const float* W2 = (const float*)d_in[5];
    const float* b2 = (const float*)d_in[6];
    float* out = (float*)d_out;

    u64 *xd, *h0, *h1;
    float *st, *wt0, *wt1, *wt2;
    cudaGetSymbolAddress((void**)&xd,  g_xd);
    cudaGetSymbolAddress((void**)&h0,  g_h0);
    cudaGetSymbolAddress((void**)&h1,  g_h1);
    cudaGetSymbolAddress((void**)&st,  g_stats);
    cudaGetSymbolAddress((void**)&wt0, g_wt0);
    cudaGetSymbolAddress((void**)&wt1, g_wt1);
    cudaGetSymbolAddress((void**)&wt2, g_wt2);

    // weights transpose + x dup: 319488 + 524288 = 843776 elems
    prep_kernel<<<3296, 256>>>(x, W0, W1, W2);

    // conv0: CIN=64  -> 256 ch, relu, dup out  (grid 4x8x32 = 1024)
    conv_kernel<C_IN, true><<<dim3(4, 8, BATCH), 128>>>(xd, wt0, b0, h0, HID0, 256);
    // conv1: CIN=256 -> 256 ch, relu, dup out  (grid 1024)
    conv_kernel<HID0, true><<<dim3(4, 8, BATCH), 128>>>(h0, wt1, b1, h1, HID1, 256);
    // conv2: CIN=256 -> 96 ch, linear, normal out (grid 4x3x32 = 384)
    conv_kernel<HID1, false><<<dim3(4, 3, BATCH), 128>>>(h1, wt2, b2, st, COUT2, 96);

    // mu fused into tri_kernel; scale_tril -> remaining 67.1M outputs
    tri_kernel<<<(BATCH * ZDIM) / 4, 256>>>(st, out);
}

// round 14
// speedup vs baseline: 1.7362x; 1.7362x over previous
#include <cuda_runtime.h>
#include <cuda_bf16.h>
#include <cstdint>
#include <math.h>

// Problem constants
#define BATCH 32
#define C_IN  64
#define T_LEN 256
#define ZDIM  32
#define HID0  256
#define HID1  256
#define COUT2 96          // 3*Z
#define MU_ELEMS (BATCH*ZDIM*T_LEN)            // 262144

typedef unsigned long long u64;

// Scratch (no allocations allowed -> __device__ globals)
__device__ float g_h0[BATCH * HID0 * T_LEN];       // 8 MB
__device__ float g_h1[BATCH * HID1 * T_LEN];       // 8 MB
__device__ float g_stats[BATCH * COUT2 * T_LEN];   // 3 MB
__device__ float g_wt0[192 * 256];                 // W0 transposed [i*3+k][o]
__device__ float g_wt1[768 * 256];                 // W1 transposed
__device__ float g_wt2[768 * 96];                  // W2 transposed (exact)

// ---------------------------------------------------------------------------
// packed-f32x2 helpers (FFMA2: only reachable via PTX fma.rn.f32x2)
// ---------------------------------------------------------------------------
__device__ __forceinline__ u64 splat2(float x) {
    u64 r; asm("mov.b64 %0,{%1,%1};" : "=l"(r) : "f"(x)); return r;
}
__device__ __forceinline__ void fma2(u64& d, u64 a, u64 b) {
    asm("fma.rn.f32x2 %0,%1,%2,%0;" : "+l"(d) : "l"(a), "l"(b));
}
__device__ __forceinline__ float2 unpk(u64 v) {
    float2 f; asm("mov.b64 {%0,%1},%2;" : "=f"(f.x), "=f"(f.y) : "l"(v)); return f;
}

// ---------------------------------------------------------------------------
// cp.async helpers
// ---------------------------------------------------------------------------
__device__ __forceinline__ unsigned int s2u(const void* p) {
    unsigned int a;
    asm("{.reg .u64 t; cvta.to.shared.u64 t,%1; cvt.u32.u64 %0,t;}" : "=r"(a) : "l"(p));
    return a;
}
__device__ __forceinline__ void cp16(void* d, const void* s) {
    asm volatile("cp.async.ca.shared.global [%0],[%1],16;" :: "r"(s2u(d)), "l"(s));
}
__device__ __forceinline__ void cp4z(void* d, const void* s, bool v) {
    int sz = v ? 4 : 0;      // src-size 0 -> zero-fill, no read
    asm volatile("cp.async.ca.shared.global [%0],[%1],4,%2;" :: "r"(s2u(d)), "l"(s), "r"(sz));
}
#define CP_COMMIT() asm volatile("cp.async.commit_group;")

// ---------------------------------------------------------------------------
// Weight transpose pre-kernel: W[o][i][k] -> Wt[(i*3+k)][o]
// ---------------------------------------------------------------------------
__global__ __launch_bounds__(256)
void transpose_w_kernel(const float* __restrict__ W0, const float* __restrict__ W1,
                        const float* __restrict__ W2)
{
    int e = blockIdx.x * 256 + threadIdx.x;
    const int N0 = 192 * 256, N1 = 768 * 256, N2 = 768 * 96;
    if (e < N0) {
        int r = e >> 8, o = e & 255;
        int i = r / 3, k = r - 3 * i;
        g_wt0[e] = W0[(o * 64 + i) * 3 + k];
    } else if (e < N0 + N1) {
        int e1 = e - N0;
        int r = e1 >> 8, o = e1 & 255;
        int i = r / 3, k = r - 3 * i;
        g_wt1[e1] = W1[(o * 256 + i) * 3 + k];
    } else if (e < N0 + N1 + N2) {
        int e2 = e - N0 - N1;
        int r = e2 / 96, o = e2 - 96 * r;
        int i = r / 3, k = r - 3 * i;
        g_wt2[e2] = W2[(o * 256 + i) * 3 + k];
    }
}

// ---------------------------------------------------------------------------
// Conv1d (K=3, SAME) tiled GEMM, packed-f32x2 math, 3-stage cp.async pipeline.
// 128 threads.  Tile 32 o x 64 t, micro-tile 4o x 4t, CI=8.
// X row layout (flat, stride 72 floats, base offset 3):
//   col 0 = x[bt-1], cols 1..64 = x[bt..bt+63], col 65 = x[bt+64]
// -> thread reads its 6 x-values contiguously: p[0], float4 at p+1 (16B
//    aligned), p[5].  No predicated selects in the inner loop.
// ---------------------------------------------------------------------------
template<int CIN, bool RELU>
__global__ __launch_bounds__(128, 8)
void conv_kernel(const float* __restrict__ X, const float* __restrict__ Wt,
                 const float* __restrict__ Bias, float* __restrict__ Y,
                 int COUT, int WSTRIDE)
{
    constexpr int TILE_O = 32;
    constexpr int TILE_T = 64;
    constexpr int CI   = 8;
    constexpr int NIT  = CIN / CI;     // >= 3
    constexpr int XROW = 72;           // floats per row (3 + 66 used + pad)
    constexpr int TTHR = TILE_T / 4;   // 16 threads along t

    __shared__ __align__(16) float Xs[3][CI * XROW];
    __shared__ __align__(16) float Ws[3][CI * 3][TILE_O];

    const int tid = threadIdx.x;
    const int tx  = tid % TTHR;
    const int ty  = tid / TTHR;        // 0..7
    const int bt  = blockIdx.x * TILE_T;
    const int bo  = blockIdx.y * TILE_O;
    const int b   = blockIdx.z;

    const float* Xb = X + (size_t)b * CIN * T_LEN;

    auto load_stage = [&](int ci0, int s) {
        const float* xb = Xb + (size_t)ci0 * T_LEN;
        // main X tile: 8 rows x 16 chunks = 128 chunks (exactly 1/thread)
        {
            int row = tid >> 4, c4 = tid & 15;
            // dst col 1+4*c4 -> flat row*72 + 4 + 4*c4 (16B aligned)
            cp16(&Xs[s][row * XROW + 4 + 4 * c4], xb + row * T_LEN + bt + 4 * c4);
        }
        // halos: side 0 -> col 0 (t=bt-1), side 1 -> col 65 (t=bt+64)
        if (tid < CI * 2) {
            int row = tid >> 1, side = tid & 1;
            int t   = side ? (bt + TILE_T) : (bt - 1);
            int col = side ? (3 + 65) : 3;
            bool ok = (t >= 0) && (t < T_LEN);
            cp4z(&Xs[s][row * XROW + col], xb + row * T_LEN + (ok ? t : 0), ok);
        }
        // W tile: 24 rows x 32 cols = 192 chunks (guarded)
        for (int idx = tid; idx < CI * 3 * TILE_O / 4; idx += 128) {
            int row = idx >> 3, c4 = idx & 7;
            cp16(&Ws[s][row][4 * c4],
                 Wt + (size_t)(3 * ci0 + row) * WSTRIDE + bo + 4 * c4);
        }
    };

    u64 acc[2][4];
#pragma unroll
    for (int p = 0; p < 2; ++p)
#pragma unroll
        for (int t = 0; t < 4; ++t) acc[p][t] = 0ull;

    load_stage(0,  0); CP_COMMIT();
    load_stage(CI, 1); CP_COMMIT();

#pragma unroll 1
    for (int it = 0; it < NIT; ++it) {
        if (it < NIT - 1) asm volatile("cp.async.wait_group 1;");
        else              asm volatile("cp.async.wait_group 0;");
        __syncthreads();                       // stage 'it' visible; compute(it-1) retired
        if (it + 2 < NIT) { load_stage((it + 2) * CI, (it + 2) % 3); CP_COMMIT(); }

        const int s = it % 3;
#pragma unroll
        for (int il = 0; il < CI; ++il) {
            const float* p = &Xs[s][il * XROW + 3 + 4 * tx];   // x[t0-1] at p[0]
            u64 xs[6];
            xs[0] = splat2(p[0]);
            float4 m = *(const float4*)(p + 1);                // 16B aligned
            xs[1] = splat2(m.x); xs[2] = splat2(m.y);
            xs[3] = splat2(m.z); xs[4] = splat2(m.w);
            xs[5] = splat2(p[5]);
#pragma unroll
            for (int k = 0; k < 3; ++k) {
                ulonglong2 w = *(const ulonglong2*)&Ws[s][il * 3 + k][4 * ty];
#pragma unroll
                for (int tt = 0; tt < 4; ++tt) {
                    fma2(acc[0][tt], w.x, xs[tt + k]);
                    fma2(acc[1][tt], w.y, xs[tt + k]);
                }
            }
        }
    }

    // epilogue: unpack pairs, bias (+relu), 1x float4 store per o-row
#pragma unroll
    for (int p = 0; p < 2; ++p) {
        int o0 = bo + 4 * ty + 2 * p;
        float blo = Bias[o0];
        float bhi = Bias[o0 + 1];
        float lo[4], hi[4];
#pragma unroll
        for (int tt = 0; tt < 4; ++tt) {
            float2 f = unpk(acc[p][tt]);
            lo[tt] = f.x + blo;
            hi[tt] = f.y + bhi;
            if (RELU) { lo[tt] = fmaxf(lo[tt], 0.f); hi[tt] = fmaxf(hi[tt], 0.f); }
        }
        float* yp = Y + ((size_t)b * COUT + o0) * T_LEN + bt + 4 * tx;
        *(float4*)yp           = make_float4(lo[0], lo[1], lo[2], lo[3]);
        *(float4*)(yp + T_LEN) = make_float4(hi[0], hi[1], hi[2], hi[3]);
    }
}

__device__ __forceinline__ float softplus_f(float x)
{
    return fmaxf(x, 0.f) + log1pf(expf(-fabsf(x)));
}

// ---------------------------------------------------------------------------
// Triangular fill, ROW-SPLIT (2 blocks per bz) + fused mu copy in half 0.
// cov_u[c][r] = (1/d_r) * prod_{k=c}^{r-1} (-s_k/d_k); scale_tril[r][c]=cov_u[c][r].
// Block = 4 (b,z) pairs x 64 thr; half h stores rows [h*128, h*128+128).
// Half 1 runs a silent product loop over rows 0..127 first (cheap FMA).
// ---------------------------------------------------------------------------
__global__ __launch_bounds__(256)
void tri_kernel(const float* __restrict__ stats, float* __restrict__ out)
{
    __shared__ float invd[4][256];
    __shared__ float gs[4][256];

    const int tid  = threadIdx.x;
    const int sub  = tid >> 6;
    const int lane = tid & 63;
    const int half = blockIdx.x & 1;
    const int bz   = (blockIdx.x >> 1) * 4 + sub;
    const int b    = bz >> 5;
    const int z    = bz & 31;
    const int c0   = lane * 4;

    // fused mu copy (half 0 only)
    if (half == 0) {
        float4 mv = *(const float4*)(stats + ((size_t)b * COUT2 + z) * T_LEN + c0);
        __stcs((float4*)(out + ((size_t)bz << 8) + c0), mv);
    }

    const float* sd = stats + ((size_t)b * COUT2 + 32 + 2 * z) * T_LEN;
    const float* ss = sd + T_LEN;

    float4 dv = *(const float4*)(sd + c0);
    float4 sv = *(const float4*)(ss + c0);
    float d0 = softplus_f(dv.x) + 1.f, d1 = softplus_f(dv.y) + 1.f;
    float d2 = softplus_f(dv.z) + 1.f, d3 = softplus_f(dv.w) + 1.f;
    float s0 = (c0 + 0 < 255) ? softplus_f(sv.x) : 0.f;
    float s1 = (c0 + 1 < 255) ? softplus_f(sv.y) : 0.f;
    float s2 = (c0 + 2 < 255) ? softplus_f(sv.z) : 0.f;
    float s3 = (c0 + 3 < 255) ? softplus_f(sv.w) : 0.f;
    invd[sub][c0 + 0] = 1.f / d0;  gs[sub][c0 + 0] = -s0 / d0;
    invd[sub][c0 + 1] = 1.f / d1;  gs[sub][c0 + 1] = -s1 / d1;
    invd[sub][c0 + 2] = 1.f / d2;  gs[sub][c0 + 2] = -s2 / d2;
    invd[sub][c0 + 3] = 1.f / d3;  gs[sub][c0 + 3] = -s3 / d3;
    __syncthreads();

    float p0 = 1.f, p1 = 1.f, p2 = 1.f, p3 = 1.f;
    const int r0 = half << 7;               // 0 or 128
    float* op = out + MU_ELEMS + ((size_t)bz << 16) + c0;

    // silent prefix-product loop (half 1 only; half 0: r0=0 -> empty)
#pragma unroll 4
    for (int r = 0; r < r0; ++r) {
        float gv = gs[sub][r];
        if (r >= c0)     p0 *= gv;
        if (r >= c0 + 1) p1 *= gv;
        if (r >= c0 + 2) p2 *= gv;
        if (r >= c0 + 3) p3 *= gv;
    }

#pragma unroll 4
    for (int r = r0; r < r0 + 128; ++r) {
        float iv = invd[sub][r];
        float gv = gs[sub][r];
        float4 v = make_float4(0.f, 0.f, 0.f, 0.f);
        if (r >= c0)     { v.x = p0 * iv; if (!isfinite(v.x)) v.x = 0.f; p0 *= gv; }
        if (r >= c0 + 1) { v.y = p1 * iv; if (!isfinite(v.y)) v.y = 0.f; p1 *= gv; }
        if (r >= c0 + 2) { v.z = p2 * iv; if (!isfinite(v.z)) v.z = 0.f; p2 *= gv; }
        if (r >= c0 + 3) { v.w = p3 * iv; if (!isfinite(v.w)) v.w = 0.f; p3 *= gv; }
        __stcs((float4*)&op[(size_t)r << 8], v);
    }
}

// ---------------------------------------------------------------------------
extern "C" void kernel_launch(void* const* d_in, const int* in_sizes, int n_in,
                              void* d_out, int out_size)
{
    const float* x  = (const float*)d_in[0];
    const float* W0 = (const float*)d_in[1];
    const float* b0 = (const float*)d_in[2];
    const float* W1 = (const float*)d_in[3];
    const float* b1 = (const float*)d_in[4];
    const float* W2 = (const float*)d_in[5];
    const float* b2 = (const float*)d_in[6];
    float* out = (float*)d_out;

    float *h0, *h1, *st, *wt0, *wt1, *wt2;
    cudaGetSymbolAddress((void**)&h0,  g_h0);
    cudaGetSymbolAddress((void**)&h1,  g_h1);
    cudaGetSymbolAddress((void**)&st,  g_stats);
    cudaGetSymbolAddress((void**)&wt0, g_wt0);
    cudaGetSymbolAddress((void**)&wt1, g_wt1);
    cudaGetSymbolAddress((void**)&wt2, g_wt2);

    // transpose all weights: (192+768)*256 + 768*96 = 319488 elems
    transpose_w_kernel<<<1248, 256>>>(W0, W1, W2);

    // conv0: CIN=64  -> 256 ch, relu   (grid 4x8x32 = 1024)
    conv_kernel<C_IN, true><<<dim3(4, 8, BATCH), 128>>>(x,  wt0, b0, h0, HID0, 256);
    // conv1: CIN=256 -> 256 ch, relu   (grid 1024)
    conv_kernel<HID0, true><<<dim3(4, 8, BATCH), 128>>>(h0, wt1, b1, h1, HID1, 256);
    // conv2: CIN=256 -> 96 ch, linear  (grid 4x3x32 = 384)
    conv_kernel<HID1, false><<<dim3(4, 3, BATCH), 128>>>(h1, wt2, b2, st, COUT2, 96);

    // mu fused into tri_kernel; scale_tril row-split: 512 blocks
    tri_kernel<<<(BATCH * ZDIM) / 2, 256>>>(st, out);
}

// round 15
// speedup vs baseline: 1.8544x; 1.0681x over previous
#include <cuda_runtime.h>
#include <cuda_bf16.h>
#include <cstdint>
#include <math.h>

// Problem constants
#define BATCH 32
#define C_IN  64
#define T_LEN 256
#define ZDIM  32
#define HID0  256
#define HID1  256
#define COUT2 96          // 3*Z
#define MU_ELEMS (BATCH*ZDIM*T_LEN)            // 262144

typedef unsigned long long u64;

// Scratch (no allocations allowed -> __device__ globals)
__device__ float g_h0[BATCH * HID0 * T_LEN];       // 8 MB
__device__ float g_h1[BATCH * HID1 * T_LEN];       // 8 MB
__device__ float g_stats[BATCH * COUT2 * T_LEN];   // 3 MB
__device__ float g_wt0[192 * 256];                 // W0 transposed [i*3+k][o]
__device__ float g_wt1[768 * 256];                 // W1 transposed
__device__ float g_wt2[768 * 96];                  // W2 transposed (exact)

// ---------------------------------------------------------------------------
// packed-f32x2 helpers (FFMA2: only reachable via PTX fma.rn.f32x2)
// ---------------------------------------------------------------------------
__device__ __forceinline__ u64 splat2(float x) {
    u64 r; asm("mov.b64 %0,{%1,%1};" : "=l"(r) : "f"(x)); return r;
}
__device__ __forceinline__ void fma2(u64& d, u64 a, u64 b) {
    asm("fma.rn.f32x2 %0,%1,%2,%0;" : "+l"(d) : "l"(a), "l"(b));
}
__device__ __forceinline__ float2 unpk(u64 v) {
    float2 f; asm("mov.b64 {%0,%1},%2;" : "=f"(f.x), "=f"(f.y) : "l"(v)); return f;
}

// ---------------------------------------------------------------------------
// cp.async helpers
// ---------------------------------------------------------------------------
__device__ __forceinline__ unsigned int s2u(const void* p) {
    unsigned int a;
    asm("{.reg .u64 t; cvta.to.shared.u64 t,%1; cvt.u32.u64 %0,t;}" : "=r"(a) : "l"(p));
    return a;
}
__device__ __forceinline__ void cp16(void* d, const void* s) {
    asm volatile("cp.async.ca.shared.global [%0],[%1],16;" :: "r"(s2u(d)), "l"(s));
}
__device__ __forceinline__ void cp4z(void* d, const void* s, bool v) {
    int sz = v ? 4 : 0;      // src-size 0 -> zero-fill, no read
    asm volatile("cp.async.ca.shared.global [%0],[%1],4,%2;" :: "r"(s2u(d)), "l"(s), "r"(sz));
}
#define CP_COMMIT() asm volatile("cp.async.commit_group;")

// ---------------------------------------------------------------------------
// Weight transpose pre-kernel: W[o][i][k] -> Wt[(i*3+k)][o]
// ---------------------------------------------------------------------------
__global__ __launch_bounds__(256)
void transpose_w_kernel(const float* __restrict__ W0, const float* __restrict__ W1,
                        const float* __restrict__ W2)
{
    int e = blockIdx.x * 256 + threadIdx.x;
    const int N0 = 192 * 256, N1 = 768 * 256, N2 = 768 * 96;
    if (e < N0) {
        int r = e >> 8, o = e & 255;
        int i = r / 3, k = r - 3 * i;
        g_wt0[e] = W0[(o * 64 + i) * 3 + k];
    } else if (e < N0 + N1) {
        int e1 = e - N0;
        int r = e1 >> 8, o = e1 & 255;
        int i = r / 3, k = r - 3 * i;
        g_wt1[e1] = W1[(o * 256 + i) * 3 + k];
    } else if (e < N0 + N1 + N2) {
        int e2 = e - N0 - N1;
        int r = e2 / 96, o = e2 - 96 * r;
        int i = r / 3, k = r - 3 * i;
        g_wt2[e2] = W2[(o * 256 + i) * 3 + k];
    }
}

// ---------------------------------------------------------------------------
// Conv1d (K=3, SAME) tiled GEMM, packed-f32x2 math, 3-stage cp.async pipeline.
// 128 threads.  Tile 32 o x 64 t, micro-tile 4o x 4t, CI=16 (halves barrier
// count vs CI=8; smem = 3*(4.6+6)KB ~= 32KB -> 7 blocks/SM, no blowup).
// X row layout (flat, stride 72 floats): col 3 = x[bt-1], cols 4..67 =
// x[bt..bt+63], col 68 = x[bt+64]; main tile 16B-aligned for cp.async.
// ---------------------------------------------------------------------------
template<int CIN, bool RELU>
__global__ __launch_bounds__(128, 7)
void conv_kernel(const float* __restrict__ X, const float* __restrict__ Wt,
                 const float* __restrict__ Bias, float* __restrict__ Y,
                 int COUT, int WSTRIDE)
{
    constexpr int TILE_O = 32;
    constexpr int TILE_T = 64;
    constexpr int CI   = 16;
    constexpr int NIT  = CIN / CI;     // 4 or 16  (>= 3)
    constexpr int XROW = 72;           // floats per row (3 pad + 66 used + pad)
    constexpr int TTHR = TILE_T / 4;   // 16 threads along t

    __shared__ __align__(16) float Xs[3][CI * XROW];
    __shared__ __align__(16) float Ws[3][CI * 3][TILE_O];

    const int tid = threadIdx.x;
    const int tx  = tid % TTHR;
    const int ty  = tid / TTHR;        // 0..7
    const int bt  = blockIdx.x * TILE_T;
    const int bo  = blockIdx.y * TILE_O;
    const int b   = blockIdx.z;

    const float* Xb = X + (size_t)b * CIN * T_LEN;

    auto load_stage = [&](int ci0, int s) {
        const float* xb = Xb + (size_t)ci0 * T_LEN;
        // main X tile: 16 rows x 16 chunks = 256 chunks (exactly 2/thread)
#pragma unroll
        for (int q = 0; q < 2; ++q) {
            int idx = tid + q * 128;
            int row = idx >> 4, c4 = idx & 15;
            cp16(&Xs[s][row * XROW + 4 + 4 * c4], xb + row * T_LEN + bt + 4 * c4);
        }
        // halos: side 0 -> col 3 (t=bt-1), side 1 -> col 68 (t=bt+64)
        if (tid < CI * 2) {
            int row = tid >> 1, side = tid & 1;
            int t   = side ? (bt + TILE_T) : (bt - 1);
            int col = side ? 68 : 3;
            bool ok = (t >= 0) && (t < T_LEN);
            cp4z(&Xs[s][row * XROW + col], xb + row * T_LEN + (ok ? t : 0), ok);
        }
        // W tile: 48 rows x 8 chunks = 384 chunks (exactly 3/thread)
#pragma unroll
        for (int q = 0; q < 3; ++q) {
            int idx = tid + q * 128;
            int row = idx >> 3, c4 = idx & 7;
            cp16(&Ws[s][row][4 * c4],
                 Wt + (size_t)(3 * ci0 + row) * WSTRIDE + bo + 4 * c4);
        }
    };

    u64 acc[2][4];
#pragma unroll
    for (int p = 0; p < 2; ++p)
#pragma unroll
        for (int t = 0; t < 4; ++t) acc[p][t] = 0ull;

    load_stage(0,  0); CP_COMMIT();
    load_stage(CI, 1); CP_COMMIT();

#pragma unroll 1
    for (int it = 0; it < NIT; ++it) {
        if (it < NIT - 1) asm volatile("cp.async.wait_group 1;");
        else              asm volatile("cp.async.wait_group 0;");
        __syncthreads();                       // stage 'it' visible; compute(it-1) retired
        if (it + 2 < NIT) { load_stage((it + 2) * CI, (it + 2) % 3); CP_COMMIT(); }

        const int s = it % 3;
#pragma unroll
        for (int il = 0; il < CI; ++il) {
            const float* p = &Xs[s][il * XROW + 3 + 4 * tx];   // x[t0-1] at p[0]
            u64 xs[6];
            xs[0] = splat2(p[0]);
            float4 m = *(const float4*)(p + 1);                // 16B aligned
            xs[1] = splat2(m.x); xs[2] = splat2(m.y);
            xs[3] = splat2(m.z); xs[4] = splat2(m.w);
            xs[5] = splat2(p[5]);
#pragma unroll
            for (int k = 0; k < 3; ++k) {
                ulonglong2 w = *(const ulonglong2*)&Ws[s][il * 3 + k][4 * ty];
#pragma unroll
                for (int tt = 0; tt < 4; ++tt) {
                    fma2(acc[0][tt], w.x, xs[tt + k]);
                    fma2(acc[1][tt], w.y, xs[tt + k]);
                }
            }
        }
    }

    // epilogue: unpack pairs, bias (+relu), 1x float4 store per o-row
#pragma unroll
    for (int p = 0; p < 2; ++p) {
        int o0 = bo + 4 * ty + 2 * p;
        float blo = Bias[o0];
        float bhi = Bias[o0 + 1];
        float lo[4], hi[4];
#pragma unroll
        for (int tt = 0; tt < 4; ++tt) {
            float2 f = unpk(acc[p][tt]);
            lo[tt] = f.x + blo;
            hi[tt] = f.y + bhi;
            if (RELU) { lo[tt] = fmaxf(lo[tt], 0.f); hi[tt] = fmaxf(hi[tt], 0.f); }
        }
        float* yp = Y + ((size_t)b * COUT + o0) * T_LEN + bt + 4 * tx;
        *(float4*)yp           = make_float4(lo[0], lo[1], lo[2], lo[3]);
        *(float4*)(yp + T_LEN) = make_float4(hi[0], hi[1], hi[2], hi[3]);
    }
}

__device__ __forceinline__ float softplus_f(float x)
{
    return fmaxf(x, 0.f) + log1pf(expf(-fabsf(x)));
}

// ---------------------------------------------------------------------------
// Triangular fill + fused mu copy  (R11 version — row-split reverted).
// cov_u[c][r] = (1/d_r) * prod_{k=c}^{r-1} (-s_k/d_k); scale_tril[r][c]=cov_u[c][r].
// Thread = 4 consecutive columns (float4 STG.cs). Block = 4 (b,z) pairs x 64 thr.
// ---------------------------------------------------------------------------
__global__ __launch_bounds__(256)
void tri_kernel(const float* __restrict__ stats, float* __restrict__ out)
{
    __shared__ float invd[4][256];
    __shared__ float gs[4][256];

    const int tid  = threadIdx.x;
    const int sub  = tid >> 6;
    const int lane = tid & 63;
    const int bz   = blockIdx.x * 4 + sub;
    const int b    = bz >> 5;
    const int z    = bz & 31;
    const int c0   = lane * 4;

    // fused mu copy
    {
        float4 mv = *(const float4*)(stats + ((size_t)b * COUT2 + z) * T_LEN + c0);
        __stcs((float4*)(out + ((size_t)bz << 8) + c0), mv);
    }

    const float* sd = stats + ((size_t)b * COUT2 + 32 + 2 * z) * T_LEN;
    const float* ss = sd + T_LEN;

    float4 dv = *(const float4*)(sd + c0);
    float4 sv = *(const float4*)(ss + c0);
    float d0 = softplus_f(dv.x) + 1.f, d1 = softplus_f(dv.y) + 1.f;
    float d2 = softplus_f(dv.z) + 1.f, d3 = softplus_f(dv.w) + 1.f;
    float s0 = (c0 + 0 < 255) ? softplus_f(sv.x) : 0.f;
    float s1 = (c0 + 1 < 255) ? softplus_f(sv.y) : 0.f;
    float s2 = (c0 + 2 < 255) ? softplus_f(sv.z) : 0.f;
    float s3 = (c0 + 3 < 255) ? softplus_f(sv.w) : 0.f;
    invd[sub][c0 + 0] = 1.f / d0;  gs[sub][c0 + 0] = -s0 / d0;
    invd[sub][c0 + 1] = 1.f / d1;  gs[sub][c0 + 1] = -s1 / d1;
    invd[sub][c0 + 2] = 1.f / d2;  gs[sub][c0 + 2] = -s2 / d2;
    invd[sub][c0 + 3] = 1.f / d3;  gs[sub][c0 + 3] = -s3 / d3;
    __syncthreads();

    float p0 = 1.f, p1 = 1.f, p2 = 1.f, p3 = 1.f;
    float* op = out + MU_ELEMS + ((size_t)bz << 16) + c0;

#pragma unroll 4
    for (int r = 0; r < 256; ++r) {
        float iv = invd[sub][r];
        float gv = gs[sub][r];
        float4 v = make_float4(0.f, 0.f, 0.f, 0.f);
        if (r >= c0)     { v.x = p0 * iv; if (!isfinite(v.x)) v.x = 0.f; p0 *= gv; }
        if (r >= c0 + 1) { v.y = p1 * iv; if (!isfinite(v.y)) v.y = 0.f; p1 *= gv; }
        if (r >= c0 + 2) { v.z = p2 * iv; if (!isfinite(v.z)) v.z = 0.f; p2 *= gv; }
        if (r >= c0 + 3) { v.w = p3 * iv; if (!isfinite(v.w)) v.w = 0.f; p3 *= gv; }
        __stcs((float4*)&op[(size_t)r << 8], v);
    }
}

// ---------------------------------------------------------------------------
extern "C" void kernel_launch(void* const* d_in, const int* in_sizes, int n_in,
                              void* d_out, int out_size)
{
    const float* x  = (const float*)d_in[0];
    const float* W0 = (const float*)d_in[1];
    const float* b0 = (const float*)d_in[2];
    const float* W1 = (const float*)d_in[3];
    const float* b1 = (const float*)d_in[4];
    const float* W2 = (const float*)d_in[5];
    const float* b2 = (const float*)d_in[6];
    float* out = (float*)d_out;

    float *h0, *h1, *st, *wt0, *wt1, *wt2;
    cudaGetSymbolAddress((void**)&h0,  g_h0);
    cudaGetSymbolAddress((void**)&h1,  g_h1);
    cudaGetSymbolAddress((void**)&st,  g_stats);
    cudaGetSymbolAddress((void**)&wt0, g_wt0);
    cudaGetSymbolAddress((void**)&wt1, g_wt1);
    cudaGetSymbolAddress((void**)&wt2, g_wt2);

    // transpose all weights: (192+768)*256 + 768*96 = 319488 elems
    transpose_w_kernel<<<1248, 256>>>(W0, W1, W2);

    // conv0: CIN=64  -> 256 ch, relu   (grid 4x8x32 = 1024, NIT=4)
    conv_kernel<C_IN, true><<<dim3(4, 8, BATCH), 128>>>(x,  wt0, b0, h0, HID0, 256);
    // conv1: CIN=256 -> 256 ch, relu   (grid 1024, NIT=16)
    conv_kernel<HID0, true><<<dim3(4, 8, BATCH), 128>>>(h0, wt1, b1, h1, HID1, 256);
    // conv2: CIN=256 -> 96 ch, linear  (grid 4x3x32 = 384, NIT=16)
    conv_kernel<HID1, false><<<dim3(4, 3, BATCH), 128>>>(h1, wt2, b2, st, COUT2, 96);

    // mu fused into tri_kernel; scale_tril -> remaining 67.1M outputs
    tri_kernel<<<(BATCH * ZDIM) / 4, 256>>>(st, out);
}